// round 5
// baseline (speedup 1.0000x reference)
#include <cuda_runtime.h>
#include <cuda_bf16.h>
#include <cstdint>
#include <math.h>

// ---------------------------------------------------------------------------
// Fixed problem: B=4, S=2048, D=DK=1024. M = B*S = 8192.
// HMMA (mma.sync bf16) bf16x3 split, fp32 accum.
// R5: 256x128 CTA tiles (512 thr), exp fused into scores epilogue,
//     normalization fused into AV A-operand load. No separate softmax.
// ---------------------------------------------------------------------------
#define BATCH 4
#define SEQ   2048
#define DIM   1024
#define DKV   1024
#define MTOT  (BATCH * SEQ)

#define TM_ 256
#define TN_ 128
#define KC  32            // bf16 elements per K-chunk (64B rows, SW64)

// ---------------- scratch (device globals; no allocation) -------------------
__device__ __nv_bfloat16 g_xh[(size_t)MTOT * DIM];
__device__ __nv_bfloat16 g_xl[(size_t)MTOT * DIM];
__device__ __nv_bfloat16 g_wth[3][(size_t)DIM * DKV];
__device__ __nv_bfloat16 g_wtl[3][(size_t)DIM * DKV];
__device__ __nv_bfloat16 g_qh[(size_t)MTOT * DKV];
__device__ __nv_bfloat16 g_ql[(size_t)MTOT * DKV];
__device__ __nv_bfloat16 g_kh[(size_t)MTOT * DKV];
__device__ __nv_bfloat16 g_kl[(size_t)MTOT * DKV];
__device__ __nv_bfloat16 g_vth[(size_t)MTOT * DKV];     // [B][DKV][SEQ]
__device__ __nv_bfloat16 g_vtl[(size_t)MTOT * DKV];
__device__ float         g_E [(size_t)BATCH * SEQ * SEQ];   // exp(scores)
__device__ float         g_rsum[(size_t)MTOT * 16];         // per-tile row sums
__device__ float         g_inv [(size_t)MTOT];              // 1/rowsum

// ---------------- PTX helpers ----------------------------------------------
static __device__ __forceinline__ uint32_t smem_u32(const void* p) {
    uint32_t a;
    asm("{ .reg .u64 t; cvta.to.shared.u64 t, %1; cvt.u32.u64 %0, t; }" : "=r"(a) : "l"(p));
    return a;
}
static __device__ __forceinline__ void cp16(uint32_t dst, const void* src) {
    asm volatile("cp.async.cg.shared.global [%0], [%1], 16;" :: "r"(dst), "l"(src) : "memory");
}
static __device__ __forceinline__ void cp_commit() {
    asm volatile("cp.async.commit_group;" ::: "memory");
}
static __device__ __forceinline__ void ldsm4(uint32_t* r, uint32_t addr) {
    asm volatile("ldmatrix.sync.aligned.m8n8.x4.shared.b16 {%0,%1,%2,%3}, [%4];"
                 : "=r"(r[0]), "=r"(r[1]), "=r"(r[2]), "=r"(r[3]) : "r"(addr));
}
static __device__ __forceinline__ void mma16816(float* c, const uint32_t* a, const uint32_t* b) {
    asm volatile(
        "mma.sync.aligned.m16n8k16.row.col.f32.bf16.bf16.f32 "
        "{%0,%1,%2,%3}, {%4,%5,%6,%7}, {%8,%9}, {%0,%1,%2,%3};"
        : "+f"(c[0]), "+f"(c[1]), "+f"(c[2]), "+f"(c[3])
        : "r"(a[0]), "r"(a[1]), "r"(a[2]), "r"(a[3]), "r"(b[0]), "r"(b[1]));
}
static __device__ __forceinline__ void sts64(uint32_t addr, uint32_t a, uint32_t b) {
    asm volatile("st.shared.v2.b32 [%0], {%1, %2};" :: "r"(addr), "r"(a), "r"(b) : "memory");
}
static __device__ __forceinline__ uint32_t sw64(uint32_t off) {
    return off ^ ((off >> 3) & 0x30);
}
static __device__ __forceinline__ void split2(float v, __nv_bfloat16& h, __nv_bfloat16& l) {
    h = __float2bfloat16(v);
    l = __float2bfloat16(v - __bfloat162float(h));
}
static __device__ __forceinline__ uint32_t packbf2(__nv_bfloat16 a, __nv_bfloat16 b) {
    __nv_bfloat162 t(a, b);
    return *reinterpret_cast<uint32_t*>(&t);
}

// Stage (48KB): Ah @0 (16K), Al @16K, Bh @32K (8K), Bl @40K. 64B rows, SW64.
#define STAGE_BYTES 49152
#define NSTAGE      3
#define SMEM_BYTES  (1024 + NSTAGE * STAGE_BYTES)

static __device__ __forceinline__ void load_chunk(
    const __nv_bfloat16* Ah, const __nv_bfloat16* Al,
    const __nv_bfloat16* Bh, const __nv_bfloat16* Bl,
    int K, int m0, int n0, int koff, uint32_t stage, int tid)
{
    #pragma unroll
    for (int j = 0; j < 2; j++) {
        int id = tid + j * 512;
        int r  = id >> 2;                       // 0..255
        int cb = (id & 3) << 4;
        uint32_t sw = sw64((uint32_t)((r << 6) + cb));
        long ao = (long)(m0 + r) * K + koff + (cb >> 1);
        cp16(stage +     0 + sw, Ah + ao);
        cp16(stage + 16384 + sw, Al + ao);
    }
    {
        int r  = tid >> 2;                      // 0..127
        int cb = (tid & 3) << 4;
        uint32_t sw = sw64((uint32_t)((r << 6) + cb));
        long bo = (long)(n0 + r) * K + koff + (cb >> 1);
        cp16(stage + 32768 + sw, Bh + bo);
        cp16(stage + 40960 + sw, Bl + bo);
    }
    cp_commit();
}

// Shared compute step over one KC chunk (identical fragment code for all GEMMs)
#define COMPUTE_CHUNK(cur)                                                       \
    _Pragma("unroll")                                                            \
    for (int kk = 0; kk < 2; kk++) {                                             \
        const uint32_t ca = (uint32_t)(aColB + kk * 32);                         \
        const uint32_t cb = (uint32_t)(bColB + kk * 32);                         \
        uint32_t bhf[2][4], blf[2][4];                                           \
        _Pragma("unroll")                                                        \
        for (int t = 0; t < 2; t++) {                                            \
            uint32_t sw = sw64((uint32_t)((bRow + t * 16) << 6) + cb);           \
            ldsm4(bhf[t], (cur) + 32768 + sw);                                   \
            ldsm4(blf[t], (cur) + 40960 + sw);                                   \
        }                                                                        \
        _Pragma("unroll")                                                        \
        for (int mi = 0; mi < 4; mi++) {                                         \
            uint32_t ahf[4], alf[4];                                             \
            uint32_t sw = sw64((uint32_t)((aRow + mi * 16) << 6) + ca);          \
            ldsm4(ahf, (cur) + sw);                                              \
            ldsm4(alf, (cur) + 16384 + sw);                                      \
            _Pragma("unroll")                                                    \
            for (int ni = 0; ni < 4; ni++) {                                     \
                const uint32_t* B2h = &bhf[ni >> 1][(ni & 1) * 2];               \
                const uint32_t* B2l = &blf[ni >> 1][(ni & 1) * 2];               \
                mma16816(acc[mi][ni], ahf, B2h);                                 \
                mma16816(acc[mi][ni], ahf, B2l);                                 \
                mma16816(acc[mi][ni], alf, B2h);                                 \
            }                                                                    \
        }                                                                        \
    }

// ---------------- main GEMM template ----------------------------------------
// EPI 0: +bias[n]; hi/lo row-major pitch DKV        (Q/K projections)
// EPI 1: +bias[n]; hi/lo transposed: Vt[b][n][seq]  (V projection)
// EPI 2: E = exp(acc/32 + mask); write E fp32 + per-tile row sums (scores)
template<int EPI>
__global__ void __launch_bounds__(512, 1)
gemm_bf16x3(const __nv_bfloat16* __restrict__ Ah, const __nv_bfloat16* __restrict__ Al,
            const __nv_bfloat16* __restrict__ Bh, const __nv_bfloat16* __restrict__ Bl,
            int K, long aBatch, long bBatch,
            const float* __restrict__ bias, const float* __restrict__ mask,
            float* __restrict__ outF, float* __restrict__ rsum,
            __nv_bfloat16* __restrict__ oh, __nv_bfloat16* __restrict__ ol)
{
    extern __shared__ char smraw[];
    const int tid = threadIdx.x;
    const int wid = tid >> 5;
    const int lid = tid & 31;
    const int z   = blockIdx.z;
    const int m0  = blockIdx.y * TM_;
    const int n0  = blockIdx.x * TN_;

    Ah += (long)z * aBatch;  Al += (long)z * aBatch;
    Bh += (long)z * bBatch;  Bl += (long)z * bBatch;

    const uint32_t smb = (smem_u32(smraw) + 1023u) & ~1023u;
    uint32_t stg[NSTAGE];
    #pragma unroll
    for (int s = 0; s < NSTAGE; s++) stg[s] = smb + s * STAGE_BYTES;

    // 16 warps: 4 (m) x 4 (n); warp tile 64 x 32
    const int wm = (wid >> 2) * 64;
    const int wn = (wid & 3) * 32;

    const int aRow  = wm + (lid & 15);
    const int aColB = (lid >> 4) << 4;
    const int bRow  = wn + (((lid >> 4) & 1) << 3) + (lid & 7);
    const int bColB = ((lid >> 3) & 1) << 4;

    float acc[4][4][4];
    #pragma unroll
    for (int mi = 0; mi < 4; mi++)
        #pragma unroll
        for (int ni = 0; ni < 4; ni++)
            #pragma unroll
            for (int r = 0; r < 4; r++) acc[mi][ni][r] = 0.0f;

    const int NC = K / KC;
    load_chunk(Ah, Al, Bh, Bl, K, m0, n0, 0, stg[0], tid);
    load_chunk(Ah, Al, Bh, Bl, K, m0, n0, KC, stg[1], tid);

    uint32_t cur = stg[0];
    int nxt = 2;
    for (int i = 0; i < NC; i++) {
        asm volatile("cp.async.wait_group 1;" ::: "memory");
        __syncthreads();
        if (i + 2 < NC)
            load_chunk(Ah, Al, Bh, Bl, K, m0, n0, (i + 2) * KC, stg[nxt], tid);
        else
            cp_commit();
        COMPUTE_CHUNK(cur);
        cur = stg[(i + 1) % NSTAGE];
        nxt = (nxt + 1) % NSTAGE;
    }
    __syncthreads();

    // ---- epilogue via padded smem tile (256 x 129 fp32 = 132KB) ------------
    float* tile = (float*)(smraw + (smb - smem_u32(smraw)));
    {
        const int r0 = lid >> 2;
        const int c0 = (lid & 3) * 2;
        #pragma unroll
        for (int mi = 0; mi < 4; mi++)
            #pragma unroll
            for (int ni = 0; ni < 4; ni++) {
                int m = wm + mi * 16 + r0;
                int n = wn + ni * 8 + c0;
                tile[m * 129 + n]           = acc[mi][ni][0];
                tile[m * 129 + n + 1]       = acc[mi][ni][1];
                tile[(m + 8) * 129 + n]     = acc[mi][ni][2];
                tile[(m + 8) * 129 + n + 1] = acc[mi][ni][3];
            }
    }
    __syncthreads();

    if (EPI == 0) {
        for (int idx = tid; idx < TM_ * TN_; idx += 512) {
            int r = idx >> 7, c = idx & 127;
            float v = tile[r * 129 + c] + bias[n0 + c];
            __nv_bfloat16 h, l; split2(v, h, l);
            long o = (long)(m0 + r) * DKV + n0 + c;
            oh[o] = h; ol[o] = l;
        }
    } else if (EPI == 1) {
        const int b = m0 >> 11, seq0 = m0 & 2047;
        for (int idx = tid; idx < TM_ * TN_; idx += 512) {
            int n = idx >> 8, mm = idx & 255;
            float v = tile[mm * 129 + n] + bias[n0 + n];
            __nv_bfloat16 h, l; split2(v, h, l);
            long o = (long)b * DKV * SEQ + (long)(n0 + n) * SEQ + seq0 + mm;
            oh[o] = h; ol[o] = l;
        }
    } else {
        // scores: E = exp(s/32 + mask); write E and per-tile row sums
        const long bo = (long)z * SEQ * SEQ;
        for (int idx = tid; idx < TM_ * TN_; idx += 512) {
            int r = idx >> 7, c = idx & 127;
            long o = bo + (long)(m0 + r) * SEQ + n0 + c;
            float e = __expf(tile[r * 129 + c] * 0.03125f + mask[o]);
            tile[r * 129 + c] = e;
            outF[o] = e;
        }
        __syncthreads();
        if (tid < 256) {
            float s = 0.0f;
            #pragma unroll 8
            for (int c = 0; c < 128; c++) s += tile[tid * 129 + c];
            rsum[((long)(z << 11) + m0 + tid) * 16 + blockIdx.x] = s;
        }
    }
}

// ---------------- 1/rowsum reduce -------------------------------------------
__global__ void __launch_bounds__(256)
inv_rows(const float* __restrict__ rsum, float* __restrict__ inv)
{
    int R = blockIdx.x * 256 + threadIdx.x;   // 0..8191
    float s = 0.0f;
    #pragma unroll
    for (int t = 0; t < 16; t++) s += rsum[(long)R * 16 + t];
    inv[R] = 1.0f / s;
}

// ---------------- AV GEMM: out = (E * inv[row]) @ Vt^T ----------------------
__global__ void __launch_bounds__(512, 1)
gemm_av(const float* __restrict__ E, const float* __restrict__ inv,
        const __nv_bfloat16* __restrict__ Bh, const __nv_bfloat16* __restrict__ Bl,
        float* __restrict__ outF)
{
    extern __shared__ char smraw[];
    const int tid = threadIdx.x;
    const int wid = tid >> 5;
    const int lid = tid & 31;
    const int z   = blockIdx.z;
    const int m0  = blockIdx.y * TM_;        // seq rows within batch
    const int n0  = blockIdx.x * TN_;        // dkv cols

    const float* Eb = E + (long)z * SEQ * SEQ;
    const float* ivb = inv + (z << 11);
    const __nv_bfloat16* Bhb = Bh + (long)z * DKV * SEQ;
    const __nv_bfloat16* Blb = Bl + (long)z * DKV * SEQ;

    const uint32_t smb = (smem_u32(smraw) + 1023u) & ~1023u;
    uint32_t stg[NSTAGE];
    #pragma unroll
    for (int s = 0; s < NSTAGE; s++) stg[s] = smb + s * STAGE_BYTES;

    const int wm = (wid >> 2) * 64;
    const int wn = (wid & 3) * 32;
    const int aRow  = wm + (lid & 15);
    const int aColB = (lid >> 4) << 4;
    const int bRow  = wn + (((lid >> 4) & 1) << 3) + (lid & 7);
    const int bColB = ((lid >> 3) & 1) << 4;

    float acc[4][4][4];
    #pragma unroll
    for (int mi = 0; mi < 4; mi++)
        #pragma unroll
        for (int ni = 0; ni < 4; ni++)
            #pragma unroll
            for (int r = 0; r < 4; r++) acc[mi][ni][r] = 0.0f;

    const int K = SEQ, NC = SEQ / KC;

    // A-side: load fp32 E, scale by inv[row], split to hi/lo, store to smem
    auto load_a = [&](int koff, uint32_t stage) {
        float4 va[4];
        int rr[4], ff[4];
        #pragma unroll
        for (int j = 0; j < 4; j++) {
            int id = tid + j * 512;
            rr[j] = id >> 3;                 // 0..255
            ff[j] = id & 7;                  // float4 index in row (8 per row)
            va[j] = *reinterpret_cast<const float4*>(
                        Eb + (long)(m0 + rr[j]) * SEQ + koff + ff[j] * 4);
        }
        #pragma unroll
        for (int j = 0; j < 4; j++) {
            float iv = ivb[m0 + rr[j]];
            float x0 = va[j].x * iv, x1 = va[j].y * iv;
            float x2 = va[j].z * iv, x3 = va[j].w * iv;
            __nv_bfloat16 h0, l0, h1, l1, h2, l2, h3, l3;
            split2(x0, h0, l0); split2(x1, h1, l1);
            split2(x2, h2, l2); split2(x3, h3, l3);
            uint32_t d = sw64((uint32_t)((rr[j] << 6) + ((ff[j] >> 1) << 4)))
                       + (uint32_t)((ff[j] & 1) << 3);
            sts64(stage +         d, packbf2(h0, h1), packbf2(h2, h3));
            sts64(stage + 16384 + d, packbf2(l0, l1), packbf2(l2, l3));
        }
    };
    auto load_b = [&](int koff, uint32_t stage) {
        int r  = tid >> 2;
        int cb = (tid & 3) << 4;
        uint32_t sw = sw64((uint32_t)((r << 6) + cb));
        long bo = (long)(n0 + r) * K + koff + (cb >> 1);
        cp16(stage + 32768 + sw, Bhb + bo);
        cp16(stage + 40960 + sw, Blb + bo);
        cp_commit();
    };

    load_a(0, stg[0]);  load_b(0, stg[0]);
    load_a(KC, stg[1]); load_b(KC, stg[1]);

    uint32_t cur = stg[0];
    int nxt = 2;
    for (int i = 0; i < NC; i++) {
        asm volatile("cp.async.wait_group 1;" ::: "memory");
        __syncthreads();
        if (i + 2 < NC) {
            load_a((i + 2) * KC, stg[nxt]);
            load_b((i + 2) * KC, stg[nxt]);
        } else {
            cp_commit();
        }
        COMPUTE_CHUNK(cur);
        cur = stg[(i + 1) % NSTAGE];
        nxt = (nxt + 1) % NSTAGE;
    }
    __syncthreads();

    float* tile = (float*)(smraw + (smb - smem_u32(smraw)));
    {
        const int r0 = lid >> 2;
        const int c0 = (lid & 3) * 2;
        #pragma unroll
        for (int mi = 0; mi < 4; mi++)
            #pragma unroll
            for (int ni = 0; ni < 4; ni++) {
                int m = wm + mi * 16 + r0;
                int n = wn + ni * 8 + c0;
                tile[m * 129 + n]           = acc[mi][ni][0];
                tile[m * 129 + n + 1]       = acc[mi][ni][1];
                tile[(m + 8) * 129 + n]     = acc[mi][ni][2];
                tile[(m + 8) * 129 + n + 1] = acc[mi][ni][3];
            }
    }
    __syncthreads();
    const long bo = (long)z * SEQ * DKV;
    for (int idx = tid; idx < TM_ * TN_; idx += 512) {
        int r = idx >> 7, c = idx & 127;
        outF[bo + (long)(m0 + r) * DKV + n0 + c] = tile[r * 129 + c];
    }
}

// ---------------- elementwise split: fp32 -> bf16 hi/lo ---------------------
__global__ void __launch_bounds__(256)
split_k(const float4* __restrict__ in, __nv_bfloat16* __restrict__ hi,
        __nv_bfloat16* __restrict__ lo, int n4)
{
    int i = blockIdx.x * 256 + threadIdx.x;
    if (i >= n4) return;
    float4 v = in[i];
    __nv_bfloat16 h0, l0, h1, l1, h2, l2, h3, l3;
    split2(v.x, h0, l0); split2(v.y, h1, l1); split2(v.z, h2, l2); split2(v.w, h3, l3);
    __nv_bfloat162* H = (__nv_bfloat162*)hi;
    __nv_bfloat162* L = (__nv_bfloat162*)lo;
    H[i * 2]     = __nv_bfloat162(h0, h1);
    H[i * 2 + 1] = __nv_bfloat162(h2, h3);
    L[i * 2]     = __nv_bfloat162(l0, l1);
    L[i * 2 + 1] = __nv_bfloat162(l2, l3);
}

// ---------------- transpose + split for W [1024,1024] -> Wt -----------------
__global__ void __launch_bounds__(256)
tsplit_k(const float* __restrict__ in, __nv_bfloat16* __restrict__ hi,
         __nv_bfloat16* __restrict__ lo)
{
    __shared__ float t[32][33];
    const int bx = blockIdx.x * 32, by = blockIdx.y * 32;
    const int tx = threadIdx.x, ty = threadIdx.y;       // block (32,8)
    #pragma unroll
    for (int k = 0; k < 32; k += 8)
        t[ty + k][tx] = in[(long)(by + ty + k) * DKV + bx + tx];
    __syncthreads();
    #pragma unroll
    for (int k = 0; k < 32; k += 8) {
        float v = t[tx][ty + k];
        __nv_bfloat16 h, l; split2(v, h, l);
        long o = (long)(bx + ty + k) * DIM + by + tx;
        hi[o] = h; lo[o] = l;
    }
}

// ---------------------------------------------------------------------------
extern "C" void kernel_launch(void* const* d_in, const int* in_sizes, int n_in,
                              void* d_out, int out_size)
{
    const float* x    = (const float*)d_in[0];
    const float* mask = (const float*)d_in[1];
    const float* Wq   = (const float*)d_in[2];
    const float* bq   = (const float*)d_in[3];
    const float* Wk   = (const float*)d_in[4];
    const float* bk   = (const float*)d_in[5];
    const float* Wv   = (const float*)d_in[6];
    const float* bv   = (const float*)d_in[7];
    float* out = (float*)d_out;

    __nv_bfloat16 *xh, *xl, *wth, *wtl, *qh, *ql, *kh, *kl, *vth, *vtl;
    float *Ep, *rsp, *ivp;
    cudaGetSymbolAddress((void**)&xh,  g_xh);
    cudaGetSymbolAddress((void**)&xl,  g_xl);
    cudaGetSymbolAddress((void**)&wth, g_wth);
    cudaGetSymbolAddress((void**)&wtl, g_wtl);
    cudaGetSymbolAddress((void**)&qh,  g_qh);
    cudaGetSymbolAddress((void**)&ql,  g_ql);
    cudaGetSymbolAddress((void**)&kh,  g_kh);
    cudaGetSymbolAddress((void**)&kl,  g_kl);
    cudaGetSymbolAddress((void**)&vth, g_vth);
    cudaGetSymbolAddress((void**)&vtl, g_vtl);
    cudaGetSymbolAddress((void**)&Ep,  g_E);
    cudaGetSymbolAddress((void**)&rsp, g_rsum);
    cudaGetSymbolAddress((void**)&ivp, g_inv);

    cudaFuncSetAttribute(gemm_bf16x3<0>, cudaFuncAttributeMaxDynamicSharedMemorySize, SMEM_BYTES);
    cudaFuncSetAttribute(gemm_bf16x3<1>, cudaFuncAttributeMaxDynamicSharedMemorySize, SMEM_BYTES);
    cudaFuncSetAttribute(gemm_bf16x3<2>, cudaFuncAttributeMaxDynamicSharedMemorySize, SMEM_BYTES);
    cudaFuncSetAttribute(gemm_av,        cudaFuncAttributeMaxDynamicSharedMemorySize, SMEM_BYTES);

    const long WSZ = (long)DIM * DKV;

    // 1) split x; transpose+split W's
    {
        int n4 = MTOT * DIM / 4;
        split_k<<<n4 / 256, 256>>>((const float4*)x, xh, xl, n4);
        dim3 tb(32, 8), tg(32, 32);
        tsplit_k<<<tg, tb>>>(Wq, wth + 0 * WSZ, wtl + 0 * WSZ);
        tsplit_k<<<tg, tb>>>(Wk, wth + 1 * WSZ, wtl + 1 * WSZ);
        tsplit_k<<<tg, tb>>>(Wv, wth + 2 * WSZ, wtl + 2 * WSZ);
    }

    dim3 blk(512);

    // 2) projections (M=8192, N=1024, K=1024)
    {
        dim3 g(DKV / TN_, MTOT / TM_, 1);
        gemm_bf16x3<0><<<g, blk, SMEM_BYTES>>>(xh, xl, wth + 0 * WSZ, wtl + 0 * WSZ,
                                               DIM, 0, 0, bq, nullptr, nullptr, nullptr, qh, ql);
        gemm_bf16x3<0><<<g, blk, SMEM_BYTES>>>(xh, xl, wth + 1 * WSZ, wtl + 1 * WSZ,
                                               DIM, 0, 0, bk, nullptr, nullptr, nullptr, kh, kl);
        gemm_bf16x3<1><<<g, blk, SMEM_BYTES>>>(xh, xl, wth + 2 * WSZ, wtl + 2 * WSZ,
                                               DIM, 0, 0, bv, nullptr, nullptr, nullptr, vth, vtl);
    }

    // 3) E = exp(Q K^T / 32 + mask), per-tile row sums   (per batch)
    {
        dim3 g(SEQ / TN_, SEQ / TM_, BATCH);
        gemm_bf16x3<2><<<g, blk, SMEM_BYTES>>>(qh, ql, kh, kl, DKV,
                                               (long)SEQ * DKV, (long)SEQ * DKV,
                                               nullptr, mask, Ep, rsp, nullptr, nullptr);
    }

    // 4) inv[row] = 1 / sum(E row)
    inv_rows<<<MTOT / 256, 256>>>(rsp, ivp);

    // 5) out = (E * inv) @ V
    {
        dim3 g(DKV / TN_, SEQ / TM_, BATCH);
        gemm_av<<<g, blk, SMEM_BYTES>>>(Ep, ivp, vth, vtl, out);
    }
}

// round 6
// speedup vs baseline: 2.7313x; 2.7313x over previous
#include <cuda_runtime.h>
#include <cuda_fp16.h>
#include <cstdint>
#include <math.h>

// ---------------------------------------------------------------------------
// Fixed problem: B=4, S=2048, D=DK=1024. M = B*S = 8192.
// R6: single-pass fp16 HMMA (mma.sync m16n8k16 f32-accum). 3x fewer MMAs
// than bf16x3. exp fused into scores epilogue; separate tiny P-normalize.
// ---------------------------------------------------------------------------
#define BATCH 4
#define SEQ   2048
#define DIM   1024
#define DKV   1024
#define MTOT  (BATCH * SEQ)

#define TILE  128
#define KC    64          // fp16 elements per K-chunk (128B rows, SW128)

// ---------------- scratch (device globals; no allocation) -------------------
__device__ __half g_x16[(size_t)MTOT * DIM];
__device__ __half g_wt16[3][(size_t)DIM * DKV];          // W^T
__device__ __half g_q16[(size_t)MTOT * DKV];
__device__ __half g_k16[(size_t)MTOT * DKV];
__device__ __half g_vt16[(size_t)MTOT * DKV];            // [B][DKV][SEQ]
__device__ float  g_E [(size_t)BATCH * SEQ * SEQ];       // exp(scores)
__device__ __half g_p16[(size_t)BATCH * SEQ * SEQ];      // normalized attn
__device__ float  g_rsum[(size_t)MTOT * 16];
__device__ float  g_inv [(size_t)MTOT];

// ---------------- PTX helpers ----------------------------------------------
static __device__ __forceinline__ uint32_t smem_u32(const void* p) {
    uint32_t a;
    asm("{ .reg .u64 t; cvta.to.shared.u64 t, %1; cvt.u32.u64 %0, t; }" : "=r"(a) : "l"(p));
    return a;
}
static __device__ __forceinline__ void cp16(uint32_t dst, const void* src) {
    asm volatile("cp.async.cg.shared.global [%0], [%1], 16;" :: "r"(dst), "l"(src) : "memory");
}
static __device__ __forceinline__ void cp_commit() {
    asm volatile("cp.async.commit_group;" ::: "memory");
}
static __device__ __forceinline__ void ldsm4(uint32_t* r, uint32_t addr) {
    asm volatile("ldmatrix.sync.aligned.m8n8.x4.shared.b16 {%0,%1,%2,%3}, [%4];"
                 : "=r"(r[0]), "=r"(r[1]), "=r"(r[2]), "=r"(r[3]) : "r"(addr));
}
static __device__ __forceinline__ void mma16816(float* c, const uint32_t* a, const uint32_t* b) {
    asm volatile(
        "mma.sync.aligned.m16n8k16.row.col.f32.f16.f16.f32 "
        "{%0,%1,%2,%3}, {%4,%5,%6,%7}, {%8,%9}, {%0,%1,%2,%3};"
        : "+f"(c[0]), "+f"(c[1]), "+f"(c[2]), "+f"(c[3])
        : "r"(a[0]), "r"(a[1]), "r"(a[2]), "r"(a[3]), "r"(b[0]), "r"(b[1]));
}
static __device__ __forceinline__ uint32_t sw128(uint32_t off) {
    return off ^ ((off >> 3) & 0x70);
}

// Stage (32KB): A @0 (16KB), B @16KB. 128 rows x 128B, SW128 swizzle.
#define STAGE_BYTES 32768
#define NSTAGE      3
#define SMEM_BYTES  (1024 + NSTAGE * STAGE_BYTES)

static __device__ __forceinline__ void load_chunk(
    const __half* A, const __half* B, int K,
    int m0, int n0, int koff, uint32_t stage, int tid)
{
    #pragma unroll
    for (int j = 0; j < 4; j++) {
        int id = tid + j * 256;                 // 0..1023
        int r  = id >> 3;                       // 0..127
        int cb = (id & 7) << 4;                 // byte col in 128B row
        uint32_t sw = sw128((uint32_t)((r << 7) + cb));
        cp16(stage +         sw, A + (long)(m0 + r) * K + koff + (cb >> 1));
        cp16(stage + 16384 + sw, B + (long)(n0 + r) * K + koff + (cb >> 1));
    }
    cp_commit();
}

// ---------------- GEMM: C[M,N] = sum_k A[m,k]*B[n,k]  (fp16 HMMA) -----------
// EPI 0: +bias[n]; fp16 row-major pitch DKV        (Q/K projections)
// EPI 1: +bias[n]; fp16 transposed: Vt[b][n][seq]  (V projection)
// EPI 2: E = exp(acc/32 + mask) fp32 + row-sum partials    (scores)
// EPI 3: fp32 out                                           (AV)
template<int EPI>
__global__ void __launch_bounds__(256, 2)
gemm_f16(const __half* __restrict__ A, const __half* __restrict__ B,
         int K, long aBatch, long bBatch,
         const float* __restrict__ bias, const float* __restrict__ mask,
         float* __restrict__ outF, float* __restrict__ rsum,
         __half* __restrict__ o16)
{
    extern __shared__ char smraw[];
    const int tid = threadIdx.x;
    const int wid = tid >> 5;
    const int lid = tid & 31;
    const int z   = blockIdx.z;
    const int m0  = blockIdx.y * TILE;
    const int n0  = blockIdx.x * TILE;

    A += (long)z * aBatch;
    B += (long)z * bBatch;

    const uint32_t smb = (smem_u32(smraw) + 1023u) & ~1023u;
    uint32_t stg[NSTAGE];
    #pragma unroll
    for (int s = 0; s < NSTAGE; s++) stg[s] = smb + s * STAGE_BYTES;

    // 8 warps: 2 (m) x 4 (n); warp tile 64 x 32
    const int wm = (wid >> 2) * 64;
    const int wn = (wid & 3) * 32;

    const int aRow  = wm + (lid & 15);
    const int aColB = (lid >> 4) << 4;
    const int bRow  = wn + (((lid >> 4) & 1) << 3) + (lid & 7);
    const int bColB = ((lid >> 3) & 1) << 4;

    float acc[4][4][4];
    #pragma unroll
    for (int mi = 0; mi < 4; mi++)
        #pragma unroll
        for (int ni = 0; ni < 4; ni++)
            #pragma unroll
            for (int r = 0; r < 4; r++) acc[mi][ni][r] = 0.0f;

    const int NC = K / KC;
    load_chunk(A, B, K, m0, n0, 0, stg[0], tid);
    load_chunk(A, B, K, m0, n0, KC, stg[1], tid);

    uint32_t cur = stg[0];
    int nxt = 2;
    for (int i = 0; i < NC; i++) {
        asm volatile("cp.async.wait_group 1;" ::: "memory");
        __syncthreads();
        if (i + 2 < NC)
            load_chunk(A, B, K, m0, n0, (i + 2) * KC, stg[nxt], tid);
        else
            cp_commit();

        #pragma unroll
        for (int kk = 0; kk < 4; kk++) {
            const uint32_t ca = (uint32_t)(aColB + kk * 32);
            const uint32_t cb = (uint32_t)(bColB + kk * 32);
            uint32_t bf[2][4];
            #pragma unroll
            for (int t = 0; t < 2; t++) {
                uint32_t sw = sw128((uint32_t)((bRow + t * 16) << 7) + cb);
                ldsm4(bf[t], cur + 16384 + sw);
            }
            #pragma unroll
            for (int mi = 0; mi < 4; mi++) {
                uint32_t af[4];
                uint32_t sw = sw128((uint32_t)((aRow + mi * 16) << 7) + ca);
                ldsm4(af, cur + sw);
                #pragma unroll
                for (int ni = 0; ni < 4; ni++)
                    mma16816(acc[mi][ni], af, &bf[ni >> 1][(ni & 1) * 2]);
            }
        }
        cur = stg[(i + 1) % NSTAGE];
        nxt = (nxt + 1) % NSTAGE;
    }
    __syncthreads();

    // ---- epilogue via padded smem tile (128 x 129 fp32 = 66KB) -------------
    float* tile = (float*)(smraw + (smb - smem_u32(smraw)));
    {
        const int r0 = lid >> 2;
        const int c0 = (lid & 3) * 2;
        #pragma unroll
        for (int mi = 0; mi < 4; mi++)
            #pragma unroll
            for (int ni = 0; ni < 4; ni++) {
                int m = wm + mi * 16 + r0;
                int n = wn + ni * 8 + c0;
                tile[m * 129 + n]           = acc[mi][ni][0];
                tile[m * 129 + n + 1]       = acc[mi][ni][1];
                tile[(m + 8) * 129 + n]     = acc[mi][ni][2];
                tile[(m + 8) * 129 + n + 1] = acc[mi][ni][3];
            }
    }
    __syncthreads();

    if (EPI == 0) {
        for (int idx = tid; idx < TILE * TILE; idx += 256) {
            int r = idx >> 7, c = idx & 127;
            float v = tile[r * 129 + c] + bias[n0 + c];
            o16[(long)(m0 + r) * DKV + n0 + c] = __float2half(v);
        }
    } else if (EPI == 1) {
        const int b = m0 >> 11, seq0 = m0 & 2047;
        for (int idx = tid; idx < TILE * TILE; idx += 256) {
            int n = idx >> 7, mm = idx & 127;
            float v = tile[mm * 129 + n] + bias[n0 + n];
            o16[(long)b * DKV * SEQ + (long)(n0 + n) * SEQ + seq0 + mm] = __float2half(v);
        }
    } else if (EPI == 2) {
        const long bo = (long)z * SEQ * SEQ;
        for (int idx = tid; idx < TILE * TILE; idx += 256) {
            int r = idx >> 7, c = idx & 127;
            long o = bo + (long)(m0 + r) * SEQ + n0 + c;
            float e = __expf(tile[r * 129 + c] * 0.03125f + mask[o]);
            tile[r * 129 + c] = e;
            outF[o] = e;
        }
        __syncthreads();
        if (tid < 128) {
            float s = 0.0f;
            #pragma unroll 8
            for (int c = 0; c < 128; c++) s += tile[tid * 129 + c];
            rsum[((long)(z << 11) + m0 + tid) * 16 + blockIdx.x] = s;
        }
    } else {
        const long bo = (long)z * SEQ * DKV;
        for (int idx = tid; idx < TILE * TILE; idx += 256) {
            int r = idx >> 7, c = idx & 127;
            outF[bo + (long)(m0 + r) * DKV + n0 + c] = tile[r * 129 + c];
        }
    }
}

// ---------------- 1/rowsum reduce -------------------------------------------
__global__ void __launch_bounds__(256)
inv_rows(const float* __restrict__ rsum, float* __restrict__ inv)
{
    int R = blockIdx.x * 256 + threadIdx.x;
    float s = 0.0f;
    #pragma unroll
    for (int t = 0; t < 16; t++) s += rsum[(long)R * 16 + t];
    inv[R] = 1.0f / s;
}

// ---------------- P normalize: p16 = E * inv[row] ---------------------------
__global__ void __launch_bounds__(256)
norm_p(const float* __restrict__ E, const float* __restrict__ inv,
       __half* __restrict__ p16)
{
    const long rb = (long)blockIdx.x * SEQ;
    const float iv = inv[blockIdx.x];
    const float4* e4 = (const float4*)(E + rb);
    __half2* p2 = (__half2*)(p16 + rb);
    int t = threadIdx.x;
    #pragma unroll
    for (int j = 0; j < 2; j++) {
        int i = t + j * 256;                   // 0..511 float4s
        float4 v = e4[i];
        p2[i * 2]     = __floats2half2_rn(v.x * iv, v.y * iv);
        p2[i * 2 + 1] = __floats2half2_rn(v.z * iv, v.w * iv);
    }
}

// ---------------- x -> fp16 --------------------------------------------------
__global__ void __launch_bounds__(256)
conv_x(const float4* __restrict__ in, __half2* __restrict__ out, int n4)
{
    int i = blockIdx.x * 256 + threadIdx.x;
    if (i >= n4) return;
    float4 v = in[i];
    out[i * 2]     = __floats2half2_rn(v.x, v.y);
    out[i * 2 + 1] = __floats2half2_rn(v.z, v.w);
}

// ---------------- transpose + convert W [1024,1024] -> Wt fp16 --------------
__global__ void __launch_bounds__(256)
tconv_w(const float* __restrict__ in, __half* __restrict__ out)
{
    __shared__ float t[32][33];
    const int bx = blockIdx.x * 32, by = blockIdx.y * 32;
    const int tx = threadIdx.x, ty = threadIdx.y;       // block (32,8)
    #pragma unroll
    for (int k = 0; k < 32; k += 8)
        t[ty + k][tx] = in[(long)(by + ty + k) * DKV + bx + tx];
    __syncthreads();
    #pragma unroll
    for (int k = 0; k < 32; k += 8)
        out[(long)(bx + ty + k) * DIM + by + tx] = __float2half(t[tx][ty + k]);
}

// ---------------------------------------------------------------------------
extern "C" void kernel_launch(void* const* d_in, const int* in_sizes, int n_in,
                              void* d_out, int out_size)
{
    const float* x    = (const float*)d_in[0];
    const float* mask = (const float*)d_in[1];
    const float* Wq   = (const float*)d_in[2];
    const float* bq   = (const float*)d_in[3];
    const float* Wk   = (const float*)d_in[4];
    const float* bk   = (const float*)d_in[5];
    const float* Wv   = (const float*)d_in[6];
    const float* bv   = (const float*)d_in[7];
    float* out = (float*)d_out;

    __half *x16, *wt16, *q16, *k16, *vt16, *p16;
    float *Ep, *rsp, *ivp;
    cudaGetSymbolAddress((void**)&x16,  g_x16);
    cudaGetSymbolAddress((void**)&wt16, g_wt16);
    cudaGetSymbolAddress((void**)&q16,  g_q16);
    cudaGetSymbolAddress((void**)&k16,  g_k16);
    cudaGetSymbolAddress((void**)&vt16, g_vt16);
    cudaGetSymbolAddress((void**)&p16,  g_p16);
    cudaGetSymbolAddress((void**)&Ep,   g_E);
    cudaGetSymbolAddress((void**)&rsp,  g_rsum);
    cudaGetSymbolAddress((void**)&ivp,  g_inv);

    cudaFuncSetAttribute(gemm_f16<0>, cudaFuncAttributeMaxDynamicSharedMemorySize, SMEM_BYTES);
    cudaFuncSetAttribute(gemm_f16<1>, cudaFuncAttributeMaxDynamicSharedMemorySize, SMEM_BYTES);
    cudaFuncSetAttribute(gemm_f16<2>, cudaFuncAttributeMaxDynamicSharedMemorySize, SMEM_BYTES);
    cudaFuncSetAttribute(gemm_f16<3>, cudaFuncAttributeMaxDynamicSharedMemorySize, SMEM_BYTES);

    const long WSZ = (long)DIM * DKV;

    // 1) convert x; transpose+convert W's
    {
        int n4 = MTOT * DIM / 4;
        conv_x<<<n4 / 256, 256>>>((const float4*)x, (__half2*)x16, n4);
        dim3 tb(32, 8), tg(32, 32);
        tconv_w<<<tg, tb>>>(Wq, wt16 + 0 * WSZ);
        tconv_w<<<tg, tb>>>(Wk, wt16 + 1 * WSZ);
        tconv_w<<<tg, tb>>>(Wv, wt16 + 2 * WSZ);
    }

    dim3 blk(256);

    // 2) projections (M=8192, N=1024, K=1024)
    {
        dim3 g(DKV / TILE, MTOT / TILE, 1);
        gemm_f16<0><<<g, blk, SMEM_BYTES>>>(x16, wt16 + 0 * WSZ, DIM, 0, 0,
                                            bq, nullptr, nullptr, nullptr, q16);
        gemm_f16<0><<<g, blk, SMEM_BYTES>>>(x16, wt16 + 1 * WSZ, DIM, 0, 0,
                                            bk, nullptr, nullptr, nullptr, k16);
        gemm_f16<1><<<g, blk, SMEM_BYTES>>>(x16, wt16 + 2 * WSZ, DIM, 0, 0,
                                            bv, nullptr, nullptr, nullptr, vt16);
    }

    // 3) E = exp(Q K^T / 32 + mask), per-tile row sums   (per batch)
    {
        dim3 g(SEQ / TILE, SEQ / TILE, BATCH);
        gemm_f16<2><<<g, blk, SMEM_BYTES>>>(q16, k16, DKV,
                                            (long)SEQ * DKV, (long)SEQ * DKV,
                                            nullptr, mask, Ep, rsp, nullptr);
    }

    // 4) inv[row]; 5) p16 = E * inv
    inv_rows<<<MTOT / 256, 256>>>(rsp, ivp);
    norm_p<<<MTOT, 256>>>(Ep, ivp, p16);

    // 6) out = P @ V
    {
        dim3 g(DKV / TILE, SEQ / TILE, BATCH);
        gemm_f16<3><<<g, blk, SMEM_BYTES>>>(p16, vt16, SEQ,
                                            (long)SEQ * SEQ, (long)DKV * SEQ,
                                            nullptr, nullptr, out, nullptr, nullptr);
    }
}

// round 7
// speedup vs baseline: 2.9513x; 1.0805x over previous
#include <cuda_runtime.h>
#include <cuda_fp16.h>
#include <cstdint>
#include <math.h>

// ---------------------------------------------------------------------------
// Fixed problem: B=4, S=2048, D=DK=1024. M = B*S = 8192.
// R7: fp16 HMMA single-pass. E stored fp16 unnormalized; softmax
// normalization folded into AV epilogue (inv[row] multiply). Projections
// merged into one z-indexed launch. norm_p kernel eliminated.
// ---------------------------------------------------------------------------
#define BATCH 4
#define SEQ   2048
#define DIM   1024
#define DKV   1024
#define MTOT  (BATCH * SEQ)

#define TILE  128
#define KC    64          // fp16 elements per K-chunk (128B rows, SW128)

// ---------------- scratch (device globals; no allocation) -------------------
__device__ __half g_x16[(size_t)MTOT * DIM];
__device__ __half g_wt16[3][(size_t)DIM * DKV];          // W^T (contiguous)
__device__ __half g_q16[(size_t)MTOT * DKV];
__device__ __half g_k16[(size_t)MTOT * DKV];
__device__ __half g_vt16[(size_t)MTOT * DKV];            // [B][DKV][SEQ]
__device__ __half g_E [(size_t)BATCH * SEQ * SEQ];       // exp(scores), fp16
__device__ float  g_rsum[(size_t)MTOT * 16];
__device__ float  g_inv [(size_t)MTOT];

// ---------------- PTX helpers ----------------------------------------------
static __device__ __forceinline__ uint32_t smem_u32(const void* p) {
    uint32_t a;
    asm("{ .reg .u64 t; cvta.to.shared.u64 t, %1; cvt.u32.u64 %0, t; }" : "=r"(a) : "l"(p));
    return a;
}
static __device__ __forceinline__ void cp16(uint32_t dst, const void* src) {
    asm volatile("cp.async.cg.shared.global [%0], [%1], 16;" :: "r"(dst), "l"(src) : "memory");
}
static __device__ __forceinline__ void cp_commit() {
    asm volatile("cp.async.commit_group;" ::: "memory");
}
static __device__ __forceinline__ void ldsm4(uint32_t* r, uint32_t addr) {
    asm volatile("ldmatrix.sync.aligned.m8n8.x4.shared.b16 {%0,%1,%2,%3}, [%4];"
                 : "=r"(r[0]), "=r"(r[1]), "=r"(r[2]), "=r"(r[3]) : "r"(addr));
}
static __device__ __forceinline__ void mma16816(float* c, const uint32_t* a, const uint32_t* b) {
    asm volatile(
        "mma.sync.aligned.m16n8k16.row.col.f32.f16.f16.f32 "
        "{%0,%1,%2,%3}, {%4,%5,%6,%7}, {%8,%9}, {%0,%1,%2,%3};"
        : "+f"(c[0]), "+f"(c[1]), "+f"(c[2]), "+f"(c[3])
        : "r"(a[0]), "r"(a[1]), "r"(a[2]), "r"(a[3]), "r"(b[0]), "r"(b[1]));
}
static __device__ __forceinline__ uint32_t sw128(uint32_t off) {
    return off ^ ((off >> 3) & 0x70);
}

// Stage (32KB): A @0 (16KB), B @16KB. 128 rows x 128B, SW128 swizzle.
#define STAGE_BYTES 32768
#define NSTAGE      3
#define SMEM_BYTES  (1024 + NSTAGE * STAGE_BYTES)

static __device__ __forceinline__ void load_chunk(
    const __half* A, const __half* B, int K,
    int m0, int n0, int koff, uint32_t stage, int tid)
{
    #pragma unroll
    for (int j = 0; j < 4; j++) {
        int id = tid + j * 256;                 // 0..1023
        int r  = id >> 3;                       // 0..127
        int cb = (id & 7) << 4;                 // byte col in 128B row
        uint32_t sw = sw128((uint32_t)((r << 7) + cb));
        cp16(stage +         sw, A + (long)(m0 + r) * K + koff + (cb >> 1));
        cp16(stage + 16384 + sw, B + (long)(n0 + r) * K + koff + (cb >> 1));
    }
    cp_commit();
}

// Shared prolog + mainloop + accumulator->tile spill (identical for all GEMMs)
#define GEMM_BODY(Aptr, Bptr, Kdim)                                              \
    extern __shared__ char smraw[];                                              \
    const int tid = threadIdx.x;                                                 \
    const int wid = tid >> 5;                                                    \
    const int lid = tid & 31;                                                    \
    const int z   = blockIdx.z;                                                  \
    const int m0  = blockIdx.y * TILE;                                           \
    const int n0  = blockIdx.x * TILE;                                           \
    const uint32_t smb = (smem_u32(smraw) + 1023u) & ~1023u;                     \
    uint32_t stg[NSTAGE];                                                        \
    _Pragma("unroll")                                                            \
    for (int s = 0; s < NSTAGE; s++) stg[s] = smb + s * STAGE_BYTES;             \
    const int wm = (wid >> 2) * 64;                                              \
    const int wn = (wid & 3) * 32;                                               \
    const int aRow  = wm + (lid & 15);                                           \
    const int aColB = (lid >> 4) << 4;                                           \
    const int bRow  = wn + (((lid >> 4) & 1) << 3) + (lid & 7);                  \
    const int bColB = ((lid >> 3) & 1) << 4;                                     \
    float acc[4][4][4];                                                          \
    _Pragma("unroll")                                                            \
    for (int mi = 0; mi < 4; mi++)                                               \
        _Pragma("unroll")                                                        \
        for (int ni = 0; ni < 4; ni++)                                           \
            _Pragma("unroll")                                                    \
            for (int r = 0; r < 4; r++) acc[mi][ni][r] = 0.0f;                   \
    const int NC = (Kdim) / KC;                                                  \
    load_chunk((Aptr), (Bptr), (Kdim), m0, n0, 0, stg[0], tid);                  \
    load_chunk((Aptr), (Bptr), (Kdim), m0, n0, KC, stg[1], tid);                 \
    uint32_t cur = stg[0];                                                       \
    int nxt = 2;                                                                 \
    for (int i = 0; i < NC; i++) {                                               \
        asm volatile("cp.async.wait_group 1;" ::: "memory");                     \
        __syncthreads();                                                         \
        if (i + 2 < NC)                                                          \
            load_chunk((Aptr), (Bptr), (Kdim), m0, n0, (i + 2) * KC, stg[nxt], tid); \
        else                                                                     \
            cp_commit();                                                         \
        _Pragma("unroll")                                                        \
        for (int kk = 0; kk < 4; kk++) {                                         \
            const uint32_t ca = (uint32_t)(aColB + kk * 32);                     \
            const uint32_t cb = (uint32_t)(bColB + kk * 32);                     \
            uint32_t bf[2][4];                                                   \
            _Pragma("unroll")                                                    \
            for (int t = 0; t < 2; t++) {                                        \
                uint32_t sw = sw128((uint32_t)((bRow + t * 16) << 7) + cb);      \
                ldsm4(bf[t], cur + 16384 + sw);                                  \
            }                                                                    \
            _Pragma("unroll")                                                    \
            for (int mi = 0; mi < 4; mi++) {                                     \
                uint32_t af[4];                                                  \
                uint32_t sw = sw128((uint32_t)((aRow + mi * 16) << 7) + ca);     \
                ldsm4(af, cur + sw);                                             \
                _Pragma("unroll")                                                \
                for (int ni = 0; ni < 4; ni++)                                   \
                    mma16816(acc[mi][ni], af, &bf[ni >> 1][(ni & 1) * 2]);       \
            }                                                                    \
        }                                                                        \
        cur = stg[(i + 1) % NSTAGE];                                             \
        nxt = (nxt + 1) % NSTAGE;                                                \
    }                                                                            \
    __syncthreads();                                                             \
    float* tile = (float*)(smraw + (smb - smem_u32(smraw)));                     \
    {                                                                            \
        const int r0 = lid >> 2;                                                 \
        const int c0 = (lid & 3) * 2;                                            \
        _Pragma("unroll")                                                        \
        for (int mi = 0; mi < 4; mi++)                                           \
            _Pragma("unroll")                                                    \
            for (int ni = 0; ni < 4; ni++) {                                     \
                int m = wm + mi * 16 + r0;                                       \
                int n = wn + ni * 8 + c0;                                        \
                tile[m * 129 + n]           = acc[mi][ni][0];                    \
                tile[m * 129 + n + 1]       = acc[mi][ni][1];                    \
                tile[(m + 8) * 129 + n]     = acc[mi][ni][2];                    \
                tile[(m + 8) * 129 + n + 1] = acc[mi][ni][3];                    \
            }                                                                    \
    }                                                                            \
    __syncthreads();

// ---------------- merged projection GEMM: z = 0(Q), 1(K), 2(V) --------------
__global__ void __launch_bounds__(256, 2)
gemm_proj(const __half* __restrict__ A, const __half* __restrict__ Wt,
          const float* __restrict__ b0, const float* __restrict__ b1,
          const float* __restrict__ b2,
          __half* __restrict__ o0, __half* __restrict__ o1,
          __half* __restrict__ o2)
{
    GEMM_BODY(A, Wt + (long)blockIdx.z * DIM * DKV, DIM)

    const float* bias = (z == 0) ? b0 : (z == 1) ? b1 : b2;
    if (z < 2) {
        __half* dst = (z == 0) ? o0 : o1;
        for (int idx = tid; idx < TILE * TILE; idx += 256) {
            int r = idx >> 7, c = idx & 127;
            float v = tile[r * 129 + c] + bias[n0 + c];
            dst[(long)(m0 + r) * DKV + n0 + c] = __float2half(v);
        }
    } else {
        // V: write transposed Vt[b][n][seq]
        const int b = m0 >> 11, seq0 = m0 & 2047;
        for (int idx = tid; idx < TILE * TILE; idx += 256) {
            int n = idx >> 7, mm = idx & 127;
            float v = tile[mm * 129 + n] + bias[n0 + n];
            o2[(long)b * DKV * SEQ + (long)(n0 + n) * SEQ + seq0 + mm] = __float2half(v);
        }
    }
}

// ---------------- scores GEMM: E = exp(QK^T/32 + mask) fp16 + rowsums -------
__global__ void __launch_bounds__(256, 2)
gemm_scores(const __half* __restrict__ Q, const __half* __restrict__ Km,
            const float* __restrict__ mask, __half* __restrict__ Eh,
            float* __restrict__ rsum)
{
    GEMM_BODY(Q + (long)blockIdx.z * SEQ * DKV,
              Km + (long)blockIdx.z * SEQ * DKV, DKV)

    const long bo = (long)z * SEQ * SEQ;
    for (int idx = tid; idx < TILE * TILE; idx += 256) {
        int r = idx >> 7, c = idx & 127;
        long o = bo + (long)(m0 + r) * SEQ + n0 + c;
        float e = __expf(tile[r * 129 + c] * 0.03125f + mask[o]);
        tile[r * 129 + c] = e;
        Eh[o] = __float2half(e);
    }
    __syncthreads();
    if (tid < 128) {
        float s = 0.0f;
        #pragma unroll 8
        for (int c = 0; c < 128; c++) s += tile[tid * 129 + c];
        rsum[((long)(z << 11) + m0 + tid) * 16 + blockIdx.x] = s;
    }
}

// ---------------- AV GEMM: out = inv[row] * (E @ V) -------------------------
__global__ void __launch_bounds__(256, 2)
gemm_av(const __half* __restrict__ E, const __half* __restrict__ Vt,
        const float* __restrict__ inv, float* __restrict__ outF)
{
    GEMM_BODY(E + (long)blockIdx.z * SEQ * SEQ,
              Vt + (long)blockIdx.z * DKV * SEQ, SEQ)

    const long bo = (long)z * SEQ * DKV;
    for (int idx = tid; idx < TILE * TILE; idx += 256) {
        int r = idx >> 7, c = idx & 127;
        float iv = inv[(z << 11) + m0 + r];
        outF[bo + (long)(m0 + r) * DKV + n0 + c] = tile[r * 129 + c] * iv;
    }
}

// ---------------- 1/rowsum reduce -------------------------------------------
__global__ void __launch_bounds__(256)
inv_rows(const float* __restrict__ rsum, float* __restrict__ inv)
{
    int R = blockIdx.x * 256 + threadIdx.x;
    float s = 0.0f;
    #pragma unroll
    for (int t = 0; t < 16; t++) s += rsum[(long)R * 16 + t];
    inv[R] = 1.0f / s;
}

// ---------------- x -> fp16 --------------------------------------------------
__global__ void __launch_bounds__(256)
conv_x(const float4* __restrict__ in, __half2* __restrict__ out, int n4)
{
    int i = blockIdx.x * 256 + threadIdx.x;
    if (i >= n4) return;
    float4 v = in[i];
    out[i * 2]     = __floats2half2_rn(v.x, v.y);
    out[i * 2 + 1] = __floats2half2_rn(v.z, v.w);
}

// ---------------- transpose + convert W (z = 0,1,2 merged) ------------------
__global__ void __launch_bounds__(256)
tconv_w(const float* __restrict__ W0, const float* __restrict__ W1,
        const float* __restrict__ W2, __half* __restrict__ out)
{
    __shared__ float t[32][33];
    const int zz = blockIdx.z;
    const float* in = (zz == 0) ? W0 : (zz == 1) ? W1 : W2;
    __half* o = out + (long)zz * DIM * DKV;
    const int bx = blockIdx.x * 32, by = blockIdx.y * 32;
    const int tx = threadIdx.x, ty = threadIdx.y;       // block (32,8)
    #pragma unroll
    for (int k = 0; k < 32; k += 8)
        t[ty + k][tx] = in[(long)(by + ty + k) * DKV + bx + tx];
    __syncthreads();
    #pragma unroll
    for (int k = 0; k < 32; k += 8)
        o[(long)(bx + ty + k) * DIM + by + tx] = __float2half(t[tx][ty + k]);
}

// ---------------------------------------------------------------------------
extern "C" void kernel_launch(void* const* d_in, const int* in_sizes, int n_in,
                              void* d_out, int out_size)
{
    const float* x    = (const float*)d_in[0];
    const float* mask = (const float*)d_in[1];
    const float* Wq   = (const float*)d_in[2];
    const float* bq   = (const float*)d_in[3];
    const float* Wk   = (const float*)d_in[4];
    const float* bk   = (const float*)d_in[5];
    const float* Wv   = (const float*)d_in[6];
    const float* bv   = (const float*)d_in[7];
    float* out = (float*)d_out;

    __half *x16, *wt16, *q16, *k16, *vt16, *Ep;
    float *rsp, *ivp;
    cudaGetSymbolAddress((void**)&x16,  g_x16);
    cudaGetSymbolAddress((void**)&wt16, g_wt16);
    cudaGetSymbolAddress((void**)&q16,  g_q16);
    cudaGetSymbolAddress((void**)&k16,  g_k16);
    cudaGetSymbolAddress((void**)&vt16, g_vt16);
    cudaGetSymbolAddress((void**)&Ep,   g_E);
    cudaGetSymbolAddress((void**)&rsp,  g_rsum);
    cudaGetSymbolAddress((void**)&ivp,  g_inv);

    cudaFuncSetAttribute(gemm_proj,   cudaFuncAttributeMaxDynamicSharedMemorySize, SMEM_BYTES);
    cudaFuncSetAttribute(gemm_scores, cudaFuncAttributeMaxDynamicSharedMemorySize, SMEM_BYTES);
    cudaFuncSetAttribute(gemm_av,     cudaFuncAttributeMaxDynamicSharedMemorySize, SMEM_BYTES);

    // 1) convert x; transpose+convert all W's (one launch)
    {
        int n4 = MTOT * DIM / 4;
        conv_x<<<n4 / 256, 256>>>((const float4*)x, (__half2*)x16, n4);
        dim3 tb(32, 8), tg(32, 32, 3);
        tconv_w<<<tg, tb>>>(Wq, Wk, Wv, wt16);
    }

    dim3 blk(256);

    // 2) Q/K/V projections in one launch (z = 0,1,2)
    {
        dim3 g(DKV / TILE, MTOT / TILE, 3);
        gemm_proj<<<g, blk, SMEM_BYTES>>>(x16, wt16, bq, bk, bv, q16, k16, vt16);
    }

    // 3) E = exp(Q K^T / 32 + mask) fp16, per-tile row sums   (per batch)
    {
        dim3 g(SEQ / TILE, SEQ / TILE, BATCH);
        gemm_scores<<<g, blk, SMEM_BYTES>>>(q16, k16, mask, Ep, rsp);
    }

    // 4) inv[row] = 1 / rowsum
    inv_rows<<<MTOT / 256, 256>>>(rsp, ivp);

    // 5) out = inv * (E @ V)
    {
        dim3 g(DKV / TILE, SEQ / TILE, BATCH);
        gemm_av<<<g, blk, SMEM_BYTES>>>(Ep, vt16, ivp, out);
    }
}

// round 8
// speedup vs baseline: 2.9992x; 1.0162x over previous
#include <cuda_runtime.h>
#include <cuda_fp16.h>
#include <cstdint>
#include <math.h>

// ---------------------------------------------------------------------------
// Fixed problem: B=4, S=2048, D=DK=1024. M = B*S = 8192.
// R8: fp16 HMMA with register fragment double-buffering (ldsm kk+1 overlaps
// MMAs of kk), XOR-folded swizzle addressing. Softmax folded as in R7.
// ---------------------------------------------------------------------------
#define BATCH 4
#define SEQ   2048
#define DIM   1024
#define DKV   1024
#define MTOT  (BATCH * SEQ)

#define TILE  128
#define KC    64          // fp16 elements per K-chunk (128B rows, SW128)

// ---------------- scratch (device globals; no allocation) -------------------
__device__ __half g_x16[(size_t)MTOT * DIM];
__device__ __half g_wt16[3][(size_t)DIM * DKV];          // W^T (contiguous)
__device__ __half g_q16[(size_t)MTOT * DKV];
__device__ __half g_k16[(size_t)MTOT * DKV];
__device__ __half g_vt16[(size_t)MTOT * DKV];            // [B][DKV][SEQ]
__device__ __half g_E [(size_t)BATCH * SEQ * SEQ];       // exp(scores), fp16
__device__ float  g_rsum[(size_t)MTOT * 16];
__device__ float  g_inv [(size_t)MTOT];

// ---------------- PTX helpers ----------------------------------------------
static __device__ __forceinline__ uint32_t smem_u32(const void* p) {
    uint32_t a;
    asm("{ .reg .u64 t; cvta.to.shared.u64 t, %1; cvt.u32.u64 %0, t; }" : "=r"(a) : "l"(p));
    return a;
}
static __device__ __forceinline__ void cp16(uint32_t dst, const void* src) {
    asm volatile("cp.async.cg.shared.global [%0], [%1], 16;" :: "r"(dst), "l"(src) : "memory");
}
static __device__ __forceinline__ void cp_commit() {
    asm volatile("cp.async.commit_group;" ::: "memory");
}
static __device__ __forceinline__ void ldsm4(uint32_t* r, uint32_t addr) {
    asm volatile("ldmatrix.sync.aligned.m8n8.x4.shared.b16 {%0,%1,%2,%3}, [%4];"
                 : "=r"(r[0]), "=r"(r[1]), "=r"(r[2]), "=r"(r[3]) : "r"(addr));
}
static __device__ __forceinline__ void mma16816(float* c, const uint32_t* a, const uint32_t* b) {
    asm volatile(
        "mma.sync.aligned.m16n8k16.row.col.f32.f16.f16.f32 "
        "{%0,%1,%2,%3}, {%4,%5,%6,%7}, {%8,%9}, {%0,%1,%2,%3};"
        : "+f"(c[0]), "+f"(c[1]), "+f"(c[2]), "+f"(c[3])
        : "r"(a[0]), "r"(a[1]), "r"(a[2]), "r"(a[3]), "r"(b[0]), "r"(b[1]));
}
static __device__ __forceinline__ uint32_t sw128(uint32_t off) {
    return off ^ ((off >> 3) & 0x70);
}

// Stage (32KB): A @0 (16KB), B @16KB. 128 rows x 128B, SW128 swizzle.
#define STAGE_BYTES 32768
#define NSTAGE      3
#define SMEM_BYTES  (1024 + NSTAGE * STAGE_BYTES)

static __device__ __forceinline__ void load_chunk(
    const __half* A, const __half* B, int K,
    int m0, int n0, int koff, uint32_t stage, int tid)
{
    #pragma unroll
    for (int j = 0; j < 4; j++) {
        int id = tid + j * 256;                 // 0..1023
        int r  = id >> 3;                       // 0..127
        int cb = (id & 7) << 4;                 // byte col in 128B row
        uint32_t sw = sw128((uint32_t)((r << 7) + cb));
        cp16(stage +         sw, A + (long)(m0 + r) * K + koff + (cb >> 1));
        cp16(stage + 16384 + sw, B + (long)(n0 + r) * K + koff + (cb >> 1));
    }
    cp_commit();
}

// Load all fragments of k-step kkv into register buffer `buf`
#define LDFRAG(kkv, buf)                                                         \
    {   const uint32_t x_ = (uint32_t)((kkv) << 5);                              \
        ldsm4(bufB[buf][0], cur + (bOff0 ^ x_));                                 \
        ldsm4(bufB[buf][1], cur + (bOff1 ^ x_));                                 \
        ldsm4(bufA[buf][0], cur + (aOff0 ^ x_));                                 \
        ldsm4(bufA[buf][1], cur + (aOff1 ^ x_));                                 \
        ldsm4(bufA[buf][2], cur + (aOff2 ^ x_));                                 \
        ldsm4(bufA[buf][3], cur + (aOff3 ^ x_)); }

#define MMAS(buf)                                                                \
    _Pragma("unroll")                                                            \
    for (int mi = 0; mi < 4; mi++)                                               \
        _Pragma("unroll")                                                        \
        for (int ni = 0; ni < 4; ni++)                                           \
            mma16816(acc[mi][ni], bufA[buf][mi], &bufB[buf][ni >> 1][(ni & 1) * 2]);

// Shared prolog + pipelined mainloop + accumulator->tile spill
#define GEMM_BODY(Aptr, Bptr, Kdim)                                              \
    extern __shared__ char smraw[];                                              \
    const int tid = threadIdx.x;                                                 \
    const int wid = tid >> 5;                                                    \
    const int lid = tid & 31;                                                    \
    const int z   = blockIdx.z;                                                  \
    const int m0  = blockIdx.y * TILE;                                           \
    const int n0  = blockIdx.x * TILE;                                           \
    const uint32_t smb = (smem_u32(smraw) + 1023u) & ~1023u;                     \
    uint32_t stg[NSTAGE];                                                        \
    _Pragma("unroll")                                                            \
    for (int s = 0; s < NSTAGE; s++) stg[s] = smb + s * STAGE_BYTES;             \
    const int wm = (wid >> 2) * 64;                                              \
    const int wn = (wid & 3) * 32;                                               \
    const int aRow  = wm + (lid & 15);                                           \
    const int aColB = (lid >> 4) << 4;                                           \
    const int bRow  = wn + (((lid >> 4) & 1) << 3) + (lid & 7);                  \
    const int bColB = ((lid >> 3) & 1) << 4;                                     \
    const uint32_t aOff0 = sw128((uint32_t)((aRow      ) << 7) + aColB);         \
    const uint32_t aOff1 = sw128((uint32_t)((aRow + 16 ) << 7) + aColB);         \
    const uint32_t aOff2 = sw128((uint32_t)((aRow + 32 ) << 7) + aColB);         \
    const uint32_t aOff3 = sw128((uint32_t)((aRow + 48 ) << 7) + aColB);         \
    const uint32_t bOff0 = sw128((uint32_t)((bRow      ) << 7) + bColB) + 16384; \
    const uint32_t bOff1 = sw128((uint32_t)((bRow + 16 ) << 7) + bColB) + 16384; \
    float acc[4][4][4];                                                          \
    _Pragma("unroll")                                                            \
    for (int mi = 0; mi < 4; mi++)                                               \
        _Pragma("unroll")                                                        \
        for (int ni = 0; ni < 4; ni++)                                           \
            _Pragma("unroll")                                                    \
            for (int r = 0; r < 4; r++) acc[mi][ni][r] = 0.0f;                   \
    uint32_t bufA[2][4][4], bufB[2][2][4];                                       \
    const int NC = (Kdim) / KC;                                                  \
    load_chunk((Aptr), (Bptr), (Kdim), m0, n0, 0, stg[0], tid);                  \
    load_chunk((Aptr), (Bptr), (Kdim), m0, n0, KC, stg[1], tid);                 \
    uint32_t cur = stg[0];                                                       \
    int nxt = 2;                                                                 \
    for (int i = 0; i < NC; i++) {                                               \
        asm volatile("cp.async.wait_group 1;" ::: "memory");                     \
        __syncthreads();                                                         \
        if (i + 2 < NC)                                                          \
            load_chunk((Aptr), (Bptr), (Kdim), m0, n0, (i + 2) * KC, stg[nxt], tid); \
        else                                                                     \
            cp_commit();                                                         \
        LDFRAG(0, 0)                                                             \
        LDFRAG(1, 1)                                                             \
        MMAS(0)                                                                  \
        LDFRAG(2, 0)                                                             \
        MMAS(1)                                                                  \
        LDFRAG(3, 1)                                                             \
        MMAS(0)                                                                  \
        MMAS(1)                                                                  \
        cur = stg[(i + 1) % NSTAGE];                                             \
        nxt = (nxt + 1) % NSTAGE;                                                \
    }                                                                            \
    __syncthreads();                                                             \
    float* tile = (float*)(smraw + (smb - smem_u32(smraw)));                     \
    {                                                                            \
        const int r0 = lid >> 2;                                                 \
        const int c0 = (lid & 3) * 2;                                            \
        _Pragma("unroll")                                                        \
        for (int mi = 0; mi < 4; mi++)                                           \
            _Pragma("unroll")                                                    \
            for (int ni = 0; ni < 4; ni++) {                                     \
                int m = wm + mi * 16 + r0;                                       \
                int n = wn + ni * 8 + c0;                                        \
                tile[m * 129 + n]           = acc[mi][ni][0];                    \
                tile[m * 129 + n + 1]       = acc[mi][ni][1];                    \
                tile[(m + 8) * 129 + n]     = acc[mi][ni][2];                    \
                tile[(m + 8) * 129 + n + 1] = acc[mi][ni][3];                    \
            }                                                                    \
    }                                                                            \
    __syncthreads();

// Wait: MMAS(0) at kk=2 position must use buffer loaded by LDFRAG(2,0) — the
// schedule above is LD0,LD1,MMA(kk0),LD2,MMA(kk1),LD3,MMA(kk2),MMA(kk3) with
// buffers 0,1,0,1: correct pairing (kk0->buf0, kk1->buf1, kk2->buf0, kk3->buf1).

// ---------------- merged projection GEMM: z = 0(Q), 1(K), 2(V) --------------
__global__ void __launch_bounds__(256, 2)
gemm_proj(const __half* __restrict__ A, const __half* __restrict__ Wt,
          const float* __restrict__ b0, const float* __restrict__ b1,
          const float* __restrict__ b2,
          __half* __restrict__ o0, __half* __restrict__ o1,
          __half* __restrict__ o2)
{
    GEMM_BODY(A, Wt + (long)blockIdx.z * DIM * DKV, DIM)

    const float* bias = (z == 0) ? b0 : (z == 1) ? b1 : b2;
    if (z < 2) {
        __half* dst = (z == 0) ? o0 : o1;
        for (int idx = tid; idx < TILE * TILE; idx += 256) {
            int r = idx >> 7, c = idx & 127;
            float v = tile[r * 129 + c] + bias[n0 + c];
            dst[(long)(m0 + r) * DKV + n0 + c] = __float2half(v);
        }
    } else {
        // V: write transposed Vt[b][n][seq]
        const int b = m0 >> 11, seq0 = m0 & 2047;
        for (int idx = tid; idx < TILE * TILE; idx += 256) {
            int n = idx >> 7, mm = idx & 127;
            float v = tile[mm * 129 + n] + bias[n0 + n];
            o2[(long)b * DKV * SEQ + (long)(n0 + n) * SEQ + seq0 + mm] = __float2half(v);
        }
    }
}

// ---------------- scores GEMM: E = exp(QK^T/32 + mask) fp16 + rowsums -------
__global__ void __launch_bounds__(256, 2)
gemm_scores(const __half* __restrict__ Q, const __half* __restrict__ Km,
            const float* __restrict__ mask, __half* __restrict__ Eh,
            float* __restrict__ rsum)
{
    GEMM_BODY(Q + (long)blockIdx.z * SEQ * DKV,
              Km + (long)blockIdx.z * SEQ * DKV, DKV)

    const long bo = (long)z * SEQ * SEQ;
    for (int idx = tid; idx < TILE * TILE; idx += 256) {
        int r = idx >> 7, c = idx & 127;
        long o = bo + (long)(m0 + r) * SEQ + n0 + c;
        float e = __expf(tile[r * 129 + c] * 0.03125f + mask[o]);
        tile[r * 129 + c] = e;
        Eh[o] = __float2half(e);
    }
    __syncthreads();
    if (tid < 128) {
        float s = 0.0f;
        #pragma unroll 8
        for (int c = 0; c < 128; c++) s += tile[tid * 129 + c];
        rsum[((long)(z << 11) + m0 + tid) * 16 + blockIdx.x] = s;
    }
}

// ---------------- AV GEMM: out = inv[row] * (E @ V) -------------------------
__global__ void __launch_bounds__(256, 2)
gemm_av(const __half* __restrict__ E, const __half* __restrict__ Vt,
        const float* __restrict__ inv, float* __restrict__ outF)
{
    GEMM_BODY(E + (long)blockIdx.z * SEQ * SEQ,
              Vt + (long)blockIdx.z * DKV * SEQ, SEQ)

    const long bo = (long)z * SEQ * DKV;
    for (int idx = tid; idx < TILE * TILE; idx += 256) {
        int r = idx >> 7, c = idx & 127;
        float iv = inv[(z << 11) + m0 + r];
        outF[bo + (long)(m0 + r) * DKV + n0 + c] = tile[r * 129 + c] * iv;
    }
}

// ---------------- 1/rowsum reduce -------------------------------------------
__global__ void __launch_bounds__(256)
inv_rows(const float* __restrict__ rsum, float* __restrict__ inv)
{
    int R = blockIdx.x * 256 + threadIdx.x;
    float s = 0.0f;
    #pragma unroll
    for (int t = 0; t < 16; t++) s += rsum[(long)R * 16 + t];
    inv[R] = 1.0f / s;
}

// ---------------- x -> fp16 --------------------------------------------------
__global__ void __launch_bounds__(256)
conv_x(const float4* __restrict__ in, __half2* __restrict__ out, int n4)
{
    int i = blockIdx.x * 256 + threadIdx.x;
    if (i >= n4) return;
    float4 v = in[i];
    out[i * 2]     = __floats2half2_rn(v.x, v.y);
    out[i * 2 + 1] = __floats2half2_rn(v.z, v.w);
}

// ---------------- transpose + convert W (z = 0,1,2 merged) ------------------
__global__ void __launch_bounds__(256)
tconv_w(const float* __restrict__ W0, const float* __restrict__ W1,
        const float* __restrict__ W2, __half* __restrict__ out)
{
    __shared__ float t[32][33];
    const int zz = blockIdx.z;
    const float* in = (zz == 0) ? W0 : (zz == 1) ? W1 : W2;
    __half* o = out + (long)zz * DIM * DKV;
    const int bx = blockIdx.x * 32, by = blockIdx.y * 32;
    const int tx = threadIdx.x, ty = threadIdx.y;       // block (32,8)
    #pragma unroll
    for (int k = 0; k < 32; k += 8)
        t[ty + k][tx] = in[(long)(by + ty + k) * DKV + bx + tx];
    __syncthreads();
    #pragma unroll
    for (int k = 0; k < 32; k += 8)
        o[(long)(bx + ty + k) * DIM + by + tx] = __float2half(t[tx][ty + k]);
}

// ---------------------------------------------------------------------------
extern "C" void kernel_launch(void* const* d_in, const int* in_sizes, int n_in,
                              void* d_out, int out_size)
{
    const float* x    = (const float*)d_in[0];
    const float* mask = (const float*)d_in[1];
    const float* Wq   = (const float*)d_in[2];
    const float* bq   = (const float*)d_in[3];
    const float* Wk   = (const float*)d_in[4];
    const float* bk   = (const float*)d_in[5];
    const float* Wv   = (const float*)d_in[6];
    const float* bv   = (const float*)d_in[7];
    float* out = (float*)d_out;

    __half *x16, *wt16, *q16, *k16, *vt16, *Ep;
    float *rsp, *ivp;
    cudaGetSymbolAddress((void**)&x16,  g_x16);
    cudaGetSymbolAddress((void**)&wt16, g_wt16);
    cudaGetSymbolAddress((void**)&q16,  g_q16);
    cudaGetSymbolAddress((void**)&k16,  g_k16);
    cudaGetSymbolAddress((void**)&vt16, g_vt16);
    cudaGetSymbolAddress((void**)&Ep,   g_E);
    cudaGetSymbolAddress((void**)&rsp,  g_rsum);
    cudaGetSymbolAddress((void**)&ivp,  g_inv);

    cudaFuncSetAttribute(gemm_proj,   cudaFuncAttributeMaxDynamicSharedMemorySize, SMEM_BYTES);
    cudaFuncSetAttribute(gemm_scores, cudaFuncAttributeMaxDynamicSharedMemorySize, SMEM_BYTES);
    cudaFuncSetAttribute(gemm_av,     cudaFuncAttributeMaxDynamicSharedMemorySize, SMEM_BYTES);

    // 1) convert x; transpose+convert all W's (one launch)
    {
        int n4 = MTOT * DIM / 4;
        conv_x<<<n4 / 256, 256>>>((const float4*)x, (__half2*)x16, n4);
        dim3 tb(32, 8), tg(32, 32, 3);
        tconv_w<<<tg, tb>>>(Wq, Wk, Wv, wt16);
    }

    dim3 blk(256);

    // 2) Q/K/V projections in one launch (z = 0,1,2)
    {
        dim3 g(DKV / TILE, MTOT / TILE, 3);
        gemm_proj<<<g, blk, SMEM_BYTES>>>(x16, wt16, bq, bk, bv, q16, k16, vt16);
    }

    // 3) E = exp(Q K^T / 32 + mask) fp16, per-tile row sums   (per batch)
    {
        dim3 g(SEQ / TILE, SEQ / TILE, BATCH);
        gemm_scores<<<g, blk, SMEM_BYTES>>>(q16, k16, mask, Ep, rsp);
    }

    // 4) inv[row] = 1 / rowsum
    inv_rows<<<MTOT / 256, 256>>>(rsp, ivp);

    // 5) out = inv * (E @ V)
    {
        dim3 g(DKV / TILE, SEQ / TILE, BATCH);
        gemm_av<<<g, blk, SMEM_BYTES>>>(Ep, vt16, ivp, out);
    }
}